// round 10
// baseline (speedup 1.0000x reference)
#include <cuda_runtime.h>

// Problem constants
#define NT    32768      // B*S tokens
#define KDIM  256        // 2*DIM
#define HALF  128        // DIM
#define VOCAB 8192

// Scratch (no cudaMalloc allowed)
__device__ float g_cnorm[VOCAB];
__device__ int   g_idx[NT];

// ---------------------------------------------------------------------------
// Kernel 0: codebook row squared norms. One warp per row (tree reduction).
// ---------------------------------------------------------------------------
__global__ void cnorm_kernel(const float* __restrict__ cb) {
    int row  = (blockIdx.x * blockDim.x + threadIdx.x) >> 5;
    int lane = threadIdx.x & 31;
    if (row >= VOCAB) return;
    const float* r = cb + (size_t)row * KDIM;
    float s = 0.f;
#pragma unroll
    for (int j = 0; j < 8; j++) {
        float v = r[j * 32 + lane];
        s += v * v;
    }
#pragma unroll
    for (int o = 16; o; o >>= 1) s += __shfl_xor_sync(0xffffffffu, s, o);
    if (lane == 0) g_cnorm[row] = s;
}

// ---------------------------------------------------------------------------
// Kernel 1: fused distance-GEMM + running argmin.
// CTA tile: 128 tokens. Loops vocab in chunks of 128, K in tiles of 16.
// 256 threads, 8x8 fp32 register microtile per thread.
// ---------------------------------------------------------------------------
#define BM 128
#define BN 128
#define BK 16

__global__ __launch_bounds__(256, 2)
void argmin_kernel(const float* __restrict__ gr,
                   const float* __restrict__ gi,
                   const float* __restrict__ cb) {
    __shared__ float As[BK][BM];   // [k][m]
    __shared__ float Bs[BK][BN];   // [k][n]

    const int tid = threadIdx.x;
    const int tx  = tid & 15;      // code group
    const int ty  = tid >> 4;      // token group
    const int m0  = blockIdx.x * BM;

    float minv[8];
    int   mini[8];
#pragma unroll
    for (int i = 0; i < 8; i++) { minv[i] = 3.4e38f; mini[i] = 0; }

    for (int n0 = 0; n0 < VOCAB; n0 += BN) {
        float acc[8][8];
#pragma unroll
        for (int i = 0; i < 8; i++)
#pragma unroll
            for (int j = 0; j < 8; j++) acc[i][j] = 0.f;

        for (int kb = 0; kb < KDIM; kb += BK) {
            // --- load A tile (z = [real | imag]) as float4 along k ---
#pragma unroll
            for (int i = 0; i < 2; i++) {
                int id = tid * 2 + i;          // 0..511 float4 slots
                int m  = id >> 2;              // 0..127
                int kq = (id & 3) * 4;         // 0,4,8,12
                int token = m0 + m;
                int kg = kb + kq;              // never straddles HALF (BK=16)
                const float* src = (kg < HALF)
                    ? (gr + (size_t)token * HALF + kg)
                    : (gi + (size_t)token * HALF + (kg - HALF));
                float4 v = *(const float4*)src;
                As[kq + 0][m] = v.x; As[kq + 1][m] = v.y;
                As[kq + 2][m] = v.z; As[kq + 3][m] = v.w;
            }
            // --- load B tile (codebook) ---
#pragma unroll
            for (int i = 0; i < 2; i++) {
                int id = tid * 2 + i;
                int n  = id >> 2;
                int kq = (id & 3) * 4;
                const float* src = cb + (size_t)(n0 + n) * KDIM + kb + kq;
                float4 v = *(const float4*)src;
                Bs[kq + 0][n] = v.x; Bs[kq + 1][n] = v.y;
                Bs[kq + 2][n] = v.z; Bs[kq + 3][n] = v.w;
            }
            __syncthreads();

#pragma unroll
            for (int kk = 0; kk < BK; kk++) {
                float a[8], b[8];
                *(float4*)(a)     = *(const float4*)&As[kk][ty * 8];
                *(float4*)(a + 4) = *(const float4*)&As[kk][ty * 8 + 4];
                *(float4*)(b)     = *(const float4*)&Bs[kk][tx * 8];
                *(float4*)(b + 4) = *(const float4*)&Bs[kk][tx * 8 + 4];
#pragma unroll
                for (int i = 0; i < 8; i++)
#pragma unroll
                    for (int j = 0; j < 8; j++)
                        acc[i][j] += a[i] * b[j];
            }
            __syncthreads();
        }

        // running argmin update: d = ||c||^2 - 2 z.c  (||z||^2 constant per token)
#pragma unroll
        for (int j = 0; j < 8; j++) {
            int v = n0 + tx * 8 + j;
            float cn = g_cnorm[v];
#pragma unroll
            for (int i = 0; i < 8; i++) {
                float d = cn - 2.0f * acc[i][j];
                if (d < minv[i]) { minv[i] = d; mini[i] = v; }
            }
        }
    }

    // cross-thread reduction: 16 tx-threads share each token row
    __syncthreads();
    float* redv = &As[0][0];               // 2048 floats  = 128 tokens x 16
    int*   redi = (int*)&Bs[0][0];         // 2048 ints
#pragma unroll
    for (int i = 0; i < 8; i++) {
        redv[(ty * 8 + i) * 16 + tx] = minv[i];
        redi[(ty * 8 + i) * 16 + tx] = mini[i];
    }
    __syncthreads();
    if (tid < BM) {
        float best = 3.4e38f; int bi = 0;
#pragma unroll
        for (int t = 0; t < 16; t++) {
            float v = redv[tid * 16 + t];
            int   x = redi[tid * 16 + t];
            if (v < best || (v == best && x < bi)) { best = v; bi = x; }
        }
        g_idx[m0 + tid] = bi;
    }
}

// ---------------------------------------------------------------------------
// Kernel 2a: zero the loss accumulator slot (guarded)
// ---------------------------------------------------------------------------
__global__ void zero_loss_kernel(float* out, long long loss_off, long long osz) {
    if (loss_off >= 0 && loss_off < osz) out[loss_off] = 0.f;
}

// ---------------------------------------------------------------------------
// Kernel 2: gather + proposal (PLANAR real/imag) + salience + vq_loss.
// One warp per token. All d_out writes bounds-guarded by osz.
// Layout (floats):
//   full planar: [reals NT*HALF][imags NT*HALF][salience NT][loss 1]
//   real-only  : [reals NT*HALF][salience NT][loss 1]  (ibase < 0)
// ---------------------------------------------------------------------------
__global__ void epilogue_kernel(const float* __restrict__ gr,
                                const float* __restrict__ gi,
                                const float* __restrict__ cb,
                                const float* __restrict__ salw,
                                const float* __restrict__ salb,
                                float* __restrict__ out,
                                long long rbase, long long ibase,
                                long long sal_off, long long loss_off,
                                long long osz) {
    int token = (blockIdx.x * blockDim.x + threadIdx.x) >> 5;
    int lane  = threadIdx.x & 31;
    int wid   = threadIdx.x >> 5;
    __shared__ float lsum[8];

    float losspart = 0.f;
    if (token < NT) {
        int v = g_idx[token];
        const float* crow = cb + (size_t)v * KDIM;
        float salpart = 0.f;
#pragma unroll
        for (int w = 0; w < 4; w++) {
            int d = w * 32 + lane;
            float cr = crow[d];
            float ci = crow[HALF + d];
            // STE forward value: z + (z_q - z), matches reference fp arithmetic
            float zr = gr[(size_t)token * HALF + d];
            float zi = gi[(size_t)token * HALF + d];
            float vr = zr + (cr - zr);
            float vi = zi + (ci - zi);
            long long ro = rbase + (long long)token * HALF + d;
            if (ro < osz) out[ro] = vr;
            if (ibase >= 0) {
                long long io = ibase + (long long)token * HALF + d;
                if (io < osz) out[io] = vi;
            }
            float dr = cr - zr, di = ci - zi;
            losspart += dr * dr + di * di;
            salpart  += vr * salw[d] + vi * salw[HALF + d];
        }
#pragma unroll
        for (int o = 16; o; o >>= 1) {
            losspart += __shfl_xor_sync(0xffffffffu, losspart, o);
            salpart  += __shfl_xor_sync(0xffffffffu, salpart, o);
        }
        if (lane == 0 && sal_off + token < osz)
            out[sal_off + token] = salpart + salb[0];
    } else {
#pragma unroll
        for (int o = 16; o; o >>= 1)
            losspart += __shfl_xor_sync(0xffffffffu, losspart, o);
    }

    if (lane == 0) lsum[wid] = losspart;
    __syncthreads();
    if (threadIdx.x == 0 && loss_off < osz) {
        float s = 0.f;
#pragma unroll
        for (int i = 0; i < 8; i++) s += lsum[i];
        // vq_loss = 1.25 * mean((z_q - z)^2) over NT*KDIM elements
        atomicAdd(out + loss_off, s * (1.25f / (float)(NT * KDIM)));
    }
}

// ---------------------------------------------------------------------------
extern "C" void kernel_launch(void* const* d_in, const int* in_sizes, int n_in,
                              void* d_out, int out_size) {
    // Metadata order = setup_inputs() dict INSERTION order (signature order):
    //   gw_real, gw_imag, codebook, sal_w, sal_b
    // Bind by element count; the FIRST 4,194,304-elem tensor is gw_real.
    const float* gw_real  = 0;
    const float* gw_imag  = 0;
    const float* codebook = 0;
    const float* sal_w    = 0;
    const float* sal_b    = 0;
    for (int i = 0; i < n_in; i++) {
        int s = in_sizes[i];
        const float* p = (const float*)d_in[i];
        if (s == NT * HALF) {            // 4,194,304: gw_real first, then gw_imag
            if (!gw_real) gw_real = p; else gw_imag = p;
        } else if (s == VOCAB * KDIM) {  // 2,097,152
            codebook = p;
        } else if (s == KDIM) {          // 256
            sal_w = p;
        } else if (s == 1) {
            sal_b = p;
        }
    }
    float* out = (float*)d_out;
    long long osz = (long long)out_size;

    // Output layout dispatch on measured out_size (floats):
    //   >= 2 planes -> planar [reals][imags][salience][loss]
    //   else        -> reals-only [reals][salience][loss]
    long long rbase = 0, ibase, sal_off, loss_off;
    const long long PLANE = (long long)NT * HALF;   // 4,194,304
    if (osz >= 2 * PLANE) {            // full planar
        ibase    = PLANE;
        sal_off  = 2 * PLANE;
        loss_off = 2 * PLANE + NT;
    } else {                           // reals-only
        ibase    = -1;
        sal_off  = PLANE;
        loss_off = PLANE + NT;
    }

    // K0: codebook norms (8192 rows, 1 warp each)
    cnorm_kernel<<<VOCAB / 8, 256>>>(codebook);

    // K1: fused GEMM + argmin (256 CTAs x 256 threads)
    argmin_kernel<<<NT / BM, 256>>>(gw_real, gw_imag, codebook);

    // K2a: init loss slot (d_out is poisoned)
    zero_loss_kernel<<<1, 1>>>(out, loss_off, osz);

    // K2: epilogue (1 warp per token)
    epilogue_kernel<<<NT / 8, 256>>>(gw_real, gw_imag, codebook,
                                     sal_w, sal_b, out,
                                     rbase, ibase, sal_off, loss_off, osz);
}

// round 11
// speedup vs baseline: 1.4167x; 1.4167x over previous
#include <cuda_runtime.h>
#include <cuda_bf16.h>

// Problem constants
#define NT    32768      // B*S tokens
#define KDIM  256        // 2*DIM
#define HALF  128        // DIM
#define VOCAB 8192
#define KEXT  768        // 3-term bf16 split: [hi|lo|hi] x [hi|hi|lo]

// Scratch (no cudaMalloc allowed)
__device__ float g_cnorm[VOCAB];
__device__ int2  g_top[NT];                              // top-2 candidate indices
__device__ __nv_bfloat16 g_A[(size_t)NT * KEXT];         // 50.3 MB
__device__ __nv_bfloat16 g_B[(size_t)VOCAB * KEXT];      // 12.6 MB

#define SW128(o) ((o) ^ (((o) >> 3) & 0x70))

// ---------------------------------------------------------------------------
// MMA helpers
// ---------------------------------------------------------------------------
__device__ __forceinline__ void ldsm4(unsigned& r0, unsigned& r1,
                                      unsigned& r2, unsigned& r3, unsigned addr) {
    asm volatile("ldmatrix.sync.aligned.m8n8.x4.shared.b16 {%0,%1,%2,%3}, [%4];"
                 : "=r"(r0), "=r"(r1), "=r"(r2), "=r"(r3) : "r"(addr));
}
__device__ __forceinline__ void mma16816(float* c, const unsigned* a, const unsigned* b) {
    asm volatile("mma.sync.aligned.m16n8k16.row.col.f32.bf16.bf16.f32 "
                 "{%0,%1,%2,%3}, {%4,%5,%6,%7}, {%8,%9}, {%0,%1,%2,%3};"
                 : "+f"(c[0]), "+f"(c[1]), "+f"(c[2]), "+f"(c[3])
                 : "r"(a[0]), "r"(a[1]), "r"(a[2]), "r"(a[3]), "r"(b[0]), "r"(b[1]));
}

// ---------------------------------------------------------------------------
// Kernel A-convert: build A_ext = [z_hi | z_lo | z_hi], z = [real|imag]
// One thread per (token, pair-of-dims).
// ---------------------------------------------------------------------------
__global__ void convertA_kernel(const float* __restrict__ gr,
                                const float* __restrict__ gi) {
    int id = blockIdx.x * blockDim.x + threadIdx.x;   // NT*64
    int t  = id >> 6;
    int d2 = (id & 63) * 2;
    float2 r  = *(const float2*)(gr + (size_t)t * HALF + d2);
    float2 im = *(const float2*)(gi + (size_t)t * HALF + d2);
    __nv_bfloat162 rh, rl, ih, il;
    rh.x = __float2bfloat16(r.x);  rh.y = __float2bfloat16(r.y);
    rl.x = __float2bfloat16(r.x - __bfloat162float(rh.x));
    rl.y = __float2bfloat16(r.y - __bfloat162float(rh.y));
    ih.x = __float2bfloat16(im.x); ih.y = __float2bfloat16(im.y);
    il.x = __float2bfloat16(im.x - __bfloat162float(ih.x));
    il.y = __float2bfloat16(im.y - __bfloat162float(ih.y));
    __nv_bfloat16* A = g_A + (size_t)t * KEXT;
    *(__nv_bfloat162*)(A +       d2) = rh;
    *(__nv_bfloat162*)(A + 128 + d2) = ih;
    *(__nv_bfloat162*)(A + 256 + d2) = rl;
    *(__nv_bfloat162*)(A + 384 + d2) = il;
    *(__nv_bfloat162*)(A + 512 + d2) = rh;
    *(__nv_bfloat162*)(A + 640 + d2) = ih;
}

// ---------------------------------------------------------------------------
// Kernel B-convert: build B_ext = [c_hi | c_hi | c_lo]
// ---------------------------------------------------------------------------
__global__ void convertB_kernel(const float* __restrict__ cb) {
    int id = blockIdx.x * blockDim.x + threadIdx.x;   // VOCAB*128
    int v  = id >> 7;
    int k2 = (id & 127) * 2;
    float2 c = *(const float2*)(cb + (size_t)v * KDIM + k2);
    __nv_bfloat162 ch, cl;
    ch.x = __float2bfloat16(c.x); ch.y = __float2bfloat16(c.y);
    cl.x = __float2bfloat16(c.x - __bfloat162float(ch.x));
    cl.y = __float2bfloat16(c.y - __bfloat162float(ch.y));
    __nv_bfloat16* B = g_B + (size_t)v * KEXT;
    *(__nv_bfloat162*)(B +       k2) = ch;
    *(__nv_bfloat162*)(B + 256 + k2) = ch;
    *(__nv_bfloat162*)(B + 512 + k2) = cl;
}

// ---------------------------------------------------------------------------
// Kernel cnorm: codebook row squared norms (fp32 exact).
// ---------------------------------------------------------------------------
__global__ void cnorm_kernel(const float* __restrict__ cb) {
    int row  = (blockIdx.x * blockDim.x + threadIdx.x) >> 5;
    int lane = threadIdx.x & 31;
    if (row >= VOCAB) return;
    const float* r = cb + (size_t)row * KDIM;
    float s = 0.f;
#pragma unroll
    for (int j = 0; j < 8; j++) { float v = r[j * 32 + lane]; s += v * v; }
#pragma unroll
    for (int o = 16; o; o >>= 1) s += __shfl_xor_sync(0xffffffffu, s, o);
    if (lane == 0) g_cnorm[row] = s;
}

// ---------------------------------------------------------------------------
// Coarse GEMM + running top-2 argmin. HMMA bf16, K=768 (3-term split).
// CTA: 128 tokens x (vocab in 128-code chunks). 8 warps = 4(M) x 2(N),
// each warp 32x64 via m16n8k16 (2 m-frags x 8 n-frags).
// ---------------------------------------------------------------------------
#define INS(v, ix, s) do { \
    if ((v) < run_v1[s]) { run_v2[s]=run_v1[s]; run_i2[s]=run_i1[s]; \
                           run_v1[s]=(v); run_i1[s]=(ix); } \
    else if ((v) < run_v2[s]) { run_v2[s]=(v); run_i2[s]=(ix); } } while (0)

__global__ __launch_bounds__(256)
void coarse_kernel() {
    __shared__ __nv_bfloat16 sA[128 * 64];   // 16 KB, 128B-swizzled rows
    __shared__ __nv_bfloat16 sB[128 * 64];   // 16 KB
    __shared__ float s_mv[128 * 2 * 2];      // [row][warpN][rank]
    __shared__ int   s_mi[128 * 2 * 2];

    const int tid  = threadIdx.x;
    const int lane = tid & 31;
    const int warp = tid >> 5;
    const int wm   = (warp >> 1) * 32;       // warp M origin
    const int wn   = (warp & 1) * 64;        // warp N origin
    const size_t m0 = (size_t)blockIdx.x * 128;

    const unsigned sAu = (unsigned)__cvta_generic_to_shared(sA);
    const unsigned sBu = (unsigned)__cvta_generic_to_shared(sB);

    float run_v1[4], run_v2[4]; int run_i1[4], run_i2[4];
#pragma unroll
    for (int s = 0; s < 4; s++) { run_v1[s] = 3.4e38f; run_v2[s] = 3.4e38f;
                                  run_i1[s] = 0;       run_i2[s] = 0; }

    for (int n0 = 0; n0 < VOCAB; n0 += 128) {
        float acc[2][8][4];
#pragma unroll
        for (int f = 0; f < 2; f++)
#pragma unroll
            for (int n = 0; n < 8; n++)
#pragma unroll
                for (int e = 0; e < 4; e++) acc[f][n][e] = 0.f;

        for (int kb = 0; kb < KEXT; kb += 64) {
            // ---- stage tiles (each thread: 4 x 16B per array) ----
#pragma unroll
            for (int tch = 0; tch < 4; tch++) {
                int i   = tid + tch * 256;          // 0..1023
                int row = i >> 3;
                int c16 = i & 7;
                int off = row * 128 + c16 * 16;
                int swo = SW128(off);
                uint4 va = *(const uint4*)(g_A + (m0 + row) * KEXT + kb + c16 * 8);
                *(uint4*)((char*)sA + swo) = va;
                uint4 vb = *(const uint4*)(g_B + (size_t)(n0 + row) * KEXT + kb + c16 * 8);
                *(uint4*)((char*)sB + swo) = vb;
            }
            __syncthreads();

#pragma unroll
            for (int ks = 0; ks < 4; ks++) {
                unsigned a[2][4], b[8][2];
#pragma unroll
                for (int f = 0; f < 2; f++) {
                    int row = wm + f * 16 + (lane & 15);
                    int kbyt = ks * 32 + (lane >> 4) * 16;
                    unsigned addr = sAu + SW128(row * 128 + kbyt);
                    ldsm4(a[f][0], a[f][1], a[f][2], a[f][3], addr);
                }
#pragma unroll
                for (int j = 0; j < 4; j++) {
                    int row = wn + j * 16 + (lane & 15);
                    int kbyt = ks * 32 + (lane >> 4) * 16;
                    unsigned addr = sBu + SW128(row * 128 + kbyt);
                    unsigned r0, r1, r2, r3;
                    ldsm4(r0, r1, r2, r3, addr);
                    b[2 * j][0] = r0; b[2 * j + 1][0] = r1;
                    b[2 * j][1] = r2; b[2 * j + 1][1] = r3;
                }
#pragma unroll
                for (int f = 0; f < 2; f++)
#pragma unroll
                    for (int n = 0; n < 8; n++)
                        mma16816(acc[f][n], a[f], b[n]);
            }
            __syncthreads();
        }

        // ---- per-thread top-2 update: d = ||c||^2 - 2 z.c ----
#pragma unroll
        for (int f = 0; f < 2; f++)
#pragma unroll
            for (int half = 0; half < 2; half++) {
                int slot = f * 2 + half;
#pragma unroll
                for (int nf = 0; nf < 8; nf++)
#pragma unroll
                    for (int e = 0; e < 2; e++) {
                        int col  = wn + nf * 8 + (lane & 3) * 2 + e;
                        int code = n0 + col;
                        float d  = g_cnorm[code] - 2.0f * acc[f][nf][half * 2 + e];
                        INS(d, code, slot);
                    }
            }
    }

    // ---- cross-lane merge within the quad sharing each row ----
#pragma unroll
    for (int s = 0; s < 4; s++) {
#pragma unroll
        for (int x = 1; x <= 2; x <<= 1) {
            float ov1 = __shfl_xor_sync(0xffffffffu, run_v1[s], x);
            int   oi1 = __shfl_xor_sync(0xffffffffu, run_i1[s], x);
            float ov2 = __shfl_xor_sync(0xffffffffu, run_v2[s], x);
            int   oi2 = __shfl_xor_sync(0xffffffffu, run_i2[s], x);
            INS(ov1, oi1, s);
            INS(ov2, oi2, s);
        }
    }

    // ---- per-warp results to smem, then cross-warp (N halves) merge ----
    if ((lane & 3) == 0) {
#pragma unroll
        for (int s = 0; s < 4; s++) {
            int r = wm + (s >> 1) * 16 + (lane >> 2) + (s & 1) * 8;
            int w = warp & 1;
            s_mv[(r * 2 + w) * 2 + 0] = run_v1[s];
            s_mv[(r * 2 + w) * 2 + 1] = run_v2[s];
            s_mi[(r * 2 + w) * 2 + 0] = run_i1[s];
            s_mi[(r * 2 + w) * 2 + 1] = run_i2[s];
        }
    }
    __syncthreads();
    if (tid < 128) {
        float v1 = s_mv[(tid * 2 + 0) * 2 + 0], v2 = s_mv[(tid * 2 + 0) * 2 + 1];
        int   i1 = s_mi[(tid * 2 + 0) * 2 + 0], i2 = s_mi[(tid * 2 + 0) * 2 + 1];
        float b1 = s_mv[(tid * 2 + 1) * 2 + 0], b2 = s_mv[(tid * 2 + 1) * 2 + 1];
        int   j1 = s_mi[(tid * 2 + 1) * 2 + 0], j2 = s_mi[(tid * 2 + 1) * 2 + 1];
        if (b1 < v1) { v2 = v1; i2 = i1; v1 = b1; i1 = j1; }
        else if (b1 < v2) { v2 = b1; i2 = j1; }
        if (b2 < v2) { v2 = b2; i2 = j2; }
        g_top[m0 + tid] = make_int2(i1, i2);
    }
}

// ---------------------------------------------------------------------------
// Kernel: zero the loss accumulator slot (guarded)
// ---------------------------------------------------------------------------
__global__ void zero_loss_kernel(float* out, long long loss_off, long long osz) {
    if (loss_off >= 0 && loss_off < osz) out[loss_off] = 0.f;
}

// ---------------------------------------------------------------------------
// Epilogue: exact fp32 rescore of top-2 candidates, then gather + planar
// proposal + salience + vq_loss. One warp per token.
// ---------------------------------------------------------------------------
__global__ void epilogue_kernel(const float* __restrict__ gr,
                                const float* __restrict__ gi,
                                const float* __restrict__ cb,
                                const float* __restrict__ salw,
                                const float* __restrict__ salb,
                                float* __restrict__ out,
                                long long rbase, long long ibase,
                                long long sal_off, long long loss_off,
                                long long osz) {
    int token = (blockIdx.x * blockDim.x + threadIdx.x) >> 5;
    int lane  = threadIdx.x & 31;
    int wid   = threadIdx.x >> 5;
    __shared__ float lsum[8];

    float losspart = 0.f;
    if (token < NT) {
        int2 cand = g_top[token];
        const float* c0 = cb + (size_t)cand.x * KDIM;
        const float* c1 = cb + (size_t)cand.y * KDIM;
        float zr[4], zi[4], c0r[4], c0i[4], c1r[4], c1i[4];
        float dot0 = 0.f, dot1 = 0.f;
#pragma unroll
        for (int w = 0; w < 4; w++) {
            int d = w * 32 + lane;
            zr[w]  = gr[(size_t)token * HALF + d];
            zi[w]  = gi[(size_t)token * HALF + d];
            c0r[w] = c0[d];  c0i[w] = c0[HALF + d];
            c1r[w] = c1[d];  c1i[w] = c1[HALF + d];
            dot0 += zr[w] * c0r[w] + zi[w] * c0i[w];
            dot1 += zr[w] * c1r[w] + zi[w] * c1i[w];
        }
#pragma unroll
        for (int o = 16; o; o >>= 1) {
            dot0 += __shfl_xor_sync(0xffffffffu, dot0, o);
            dot1 += __shfl_xor_sync(0xffffffffu, dot1, o);
        }
        float d0 = g_cnorm[cand.x] - 2.0f * dot0;
        float d1 = g_cnorm[cand.y] - 2.0f * dot1;
        bool take1 = (d1 < d0) || (d1 == d0 && cand.y < cand.x);

        float salpart = 0.f;
#pragma unroll
        for (int w = 0; w < 4; w++) {
            int d = w * 32 + lane;
            float cr = take1 ? c1r[w] : c0r[w];
            float ci = take1 ? c1i[w] : c0i[w];
            float vr = zr[w] + (cr - zr[w]);
            float vi = zi[w] + (ci - zi[w]);
            long long ro = rbase + (long long)token * HALF + d;
            if (ro < osz) out[ro] = vr;
            if (ibase >= 0) {
                long long io = ibase + (long long)token * HALF + d;
                if (io < osz) out[io] = vi;
            }
            float dr = cr - zr[w], di = ci - zi[w];
            losspart += dr * dr + di * di;
            salpart  += vr * salw[d] + vi * salw[HALF + d];
        }
#pragma unroll
        for (int o = 16; o; o >>= 1) {
            losspart += __shfl_xor_sync(0xffffffffu, losspart, o);
            salpart  += __shfl_xor_sync(0xffffffffu, salpart, o);
        }
        if (lane == 0 && sal_off + token < osz)
            out[sal_off + token] = salpart + salb[0];
    } else {
#pragma unroll
        for (int o = 16; o; o >>= 1)
            losspart += __shfl_xor_sync(0xffffffffu, losspart, o);
    }

    if (lane == 0) lsum[wid] = losspart;
    __syncthreads();
    if (threadIdx.x == 0 && loss_off < osz) {
        float s = 0.f;
#pragma unroll
        for (int i = 0; i < 8; i++) s += lsum[i];
        atomicAdd(out + loss_off, s * (1.25f / (float)(NT * KDIM)));
    }
}

// ---------------------------------------------------------------------------
extern "C" void kernel_launch(void* const* d_in, const int* in_sizes, int n_in,
                              void* d_out, int out_size) {
    // Signature-order binding (validated R10): gw_real, gw_imag, codebook, sal_w, sal_b
    const float* gw_real  = 0;
    const float* gw_imag  = 0;
    const float* codebook = 0;
    const float* sal_w    = 0;
    const float* sal_b    = 0;
    for (int i = 0; i < n_in; i++) {
        int s = in_sizes[i];
        const float* p = (const float*)d_in[i];
        if (s == NT * HALF) { if (!gw_real) gw_real = p; else gw_imag = p; }
        else if (s == VOCAB * KDIM) codebook = p;
        else if (s == KDIM)         sal_w = p;
        else if (s == 1)            sal_b = p;
    }
    float* out = (float*)d_out;
    long long osz = (long long)out_size;

    // Planar output layout (validated R10)
    long long rbase = 0, ibase, sal_off, loss_off;
    const long long PLANE = (long long)NT * HALF;
    if (osz >= 2 * PLANE) { ibase = PLANE; sal_off = 2 * PLANE; loss_off = 2 * PLANE + NT; }
    else                  { ibase = -1;    sal_off = PLANE;     loss_off = PLANE + NT; }

    convertA_kernel<<<(NT * 64) / 256, 256>>>(gw_real, gw_imag);
    convertB_kernel<<<(VOCAB * 128) / 256, 256>>>(codebook);
    cnorm_kernel<<<VOCAB / 8, 256>>>(codebook);

    coarse_kernel<<<NT / 128, 256>>>();

    zero_loss_kernel<<<1, 1>>>(out, loss_off, osz);
    epilogue_kernel<<<NT / 8, 256>>>(gw_real, gw_imag, codebook,
                                     sal_w, sal_b, out,
                                     rbase, ibase, sal_off, loss_off, osz);
}

// round 12
// speedup vs baseline: 4.5519x; 3.2129x over previous
#include <cuda_runtime.h>
#include <cuda_bf16.h>

// Problem constants
#define NT    32768      // B*S tokens
#define KDIM  256        // 2*DIM
#define HALF  128        // DIM
#define VOCAB 8192
#define KB    512        // bytes per smem row (256 bf16)

// Scratch (no cudaMalloc allowed)
__device__ float g_cnorm[VOCAB];
__device__ int4  g_top4[NT];                         // top-4 coarse candidates
__device__ __nv_bfloat16 g_A[(size_t)NT * KDIM];     // 16.8 MB
__device__ __nv_bfloat16 g_B[(size_t)VOCAB * KDIM];  // 4.2 MB

// ---------------------------------------------------------------------------
// smem swizzle for 512B rows: XOR col bits[6:4] with row bits[2:0]
// (8 consecutive rows at same col -> 8 distinct 16B groups: ldmatrix clean)
// ---------------------------------------------------------------------------
__device__ __forceinline__ unsigned swz(int row, int colByte) {
    return (unsigned)(row * KB + (colByte ^ ((row & 7) << 4)));
}

__device__ __forceinline__ void ldsm4(unsigned& r0, unsigned& r1,
                                      unsigned& r2, unsigned& r3, unsigned addr) {
    asm volatile("ldmatrix.sync.aligned.m8n8.x4.shared.b16 {%0,%1,%2,%3}, [%4];"
                 : "=r"(r0), "=r"(r1), "=r"(r2), "=r"(r3) : "r"(addr));
}
__device__ __forceinline__ void mma16816(float* c, const unsigned* a, const unsigned* b) {
    asm volatile("mma.sync.aligned.m16n8k16.row.col.f32.bf16.bf16.f32 "
                 "{%0,%1,%2,%3}, {%4,%5,%6,%7}, {%8,%9}, {%0,%1,%2,%3};"
                 : "+f"(c[0]), "+f"(c[1]), "+f"(c[2]), "+f"(c[3])
                 : "r"(a[0]), "r"(a[1]), "r"(a[2]), "r"(a[3]), "r"(b[0]), "r"(b[1]));
}
__device__ __forceinline__ void cp16(unsigned saddr, const void* gaddr) {
    asm volatile("cp.async.cg.shared.global [%0], [%1], 16;" :: "r"(saddr), "l"(gaddr));
}
#define CP_COMMIT() asm volatile("cp.async.commit_group;")
#define CP_WAIT0()  asm volatile("cp.async.wait_group 0;")

// ---------------------------------------------------------------------------
// Convert kernels: fp32 -> bf16 (pure, no split)
// ---------------------------------------------------------------------------
__global__ void convertA_kernel(const float* __restrict__ gr,
                                const float* __restrict__ gi) {
    int id = blockIdx.x * blockDim.x + threadIdx.x;   // NT*64
    int t  = id >> 6;
    int d2 = (id & 63) * 2;
    float2 r  = *(const float2*)(gr + (size_t)t * HALF + d2);
    float2 im = *(const float2*)(gi + (size_t)t * HALF + d2);
    __nv_bfloat162 rh, ih;
    rh.x = __float2bfloat16(r.x);  rh.y = __float2bfloat16(r.y);
    ih.x = __float2bfloat16(im.x); ih.y = __float2bfloat16(im.y);
    __nv_bfloat16* A = g_A + (size_t)t * KDIM;
    *(__nv_bfloat162*)(A + d2)        = rh;
    *(__nv_bfloat162*)(A + HALF + d2) = ih;
}

__global__ void convertB_kernel(const float* __restrict__ cb) {
    int id = blockIdx.x * blockDim.x + threadIdx.x;   // VOCAB*128
    int v  = id >> 7;
    int k2 = (id & 127) * 2;
    float2 c = *(const float2*)(cb + (size_t)v * KDIM + k2);
    __nv_bfloat162 ch;
    ch.x = __float2bfloat16(c.x); ch.y = __float2bfloat16(c.y);
    *(__nv_bfloat162*)(g_B + (size_t)v * KDIM + k2) = ch;
}

// ---------------------------------------------------------------------------
// cnorm: exact fp32 codebook row norms
// ---------------------------------------------------------------------------
__global__ void cnorm_kernel(const float* __restrict__ cb) {
    int row  = (blockIdx.x * blockDim.x + threadIdx.x) >> 5;
    int lane = threadIdx.x & 31;
    if (row >= VOCAB) return;
    const float* r = cb + (size_t)row * KDIM;
    float s = 0.f;
#pragma unroll
    for (int j = 0; j < 8; j++) { float v = r[j * 32 + lane]; s += v * v; }
#pragma unroll
    for (int o = 16; o; o >>= 1) s += __shfl_xor_sync(0xffffffffu, s, o);
    if (lane == 0) g_cnorm[row] = s;
}

// ---------------------------------------------------------------------------
// Coarse GEMM + top-4 argmin. Pure bf16, K=256.
// CTA: 128 tokens, A resident in smem; vocab streamed 128 codes/chunk with
// cp.async double buffering. 8 warps = 4(M) x 2(N), warp tile 32x64.
// Score = -0.5*||c||^2 + z.c  (maximize)  [acc initialized with -0.5 cnorm]
// ---------------------------------------------------------------------------
#define INS3(v, ix, s) do {                                              \
    if ((v) > run_v1[s]) { run_v3[s]=run_v2[s]; run_i3[s]=run_i2[s];     \
                           run_v2[s]=run_v1[s]; run_i2[s]=run_i1[s];     \
                           run_v1[s]=(v); run_i1[s]=(ix); }              \
    else if ((v) > run_v2[s]) { run_v3[s]=run_v2[s]; run_i3[s]=run_i2[s];\
                                run_v2[s]=(v); run_i2[s]=(ix); }         \
    else if ((v) > run_v3[s]) { run_v3[s]=(v); run_i3[s]=(ix); } } while (0)

__global__ __launch_bounds__(256, 1)
void coarse_kernel() {
    extern __shared__ char dsm[];
    // [0,64K): sA   [64K,128K): sB0   [128K,192K): sB1
    const unsigned sAu  = (unsigned)__cvta_generic_to_shared(dsm);
    const unsigned sB0u = sAu + 65536;

    const int tid  = threadIdx.x;
    const int lane = tid & 31;
    const int warp = tid >> 5;
    const int wm   = (warp >> 1) * 32;
    const int wn   = (warp & 1) * 64;
    const size_t m0 = (size_t)blockIdx.x * 128;

    // ---- prologue: A tile (whole K) + first B tile via cp.async ----
#pragma unroll
    for (int i = 0; i < 16; i++) {
        int c   = i * 256 + tid;      // 0..4095 16B chunks
        int row = c >> 5;
        int c16 = c & 31;
        cp16(sAu + swz(row, c16 * 16),  g_A + (m0 + row) * KDIM + c16 * 8);
        cp16(sB0u + swz(row, c16 * 16), g_B + (size_t)row * KDIM + c16 * 8);
    }
    CP_COMMIT();
    CP_WAIT0();
    __syncthreads();

    float run_v1[4], run_v2[4], run_v3[4];
    int   run_i1[4], run_i2[4], run_i3[4];
#pragma unroll
    for (int s = 0; s < 4; s++) {
        run_v1[s] = -3.4e38f; run_v2[s] = -3.4e38f; run_v3[s] = -3.4e38f;
        run_i1[s] = 0; run_i2[s] = 0; run_i3[s] = 0;
    }

    const int colb = wn + (lane & 3) * 2;   // thread's even col base within tile

    for (int nc = 0; nc < VOCAB / 128; nc++) {
        const unsigned sBcur = sB0u + (unsigned)((nc & 1) * 65536);
        // prefetch next B tile into the other buffer
        if (nc + 1 < VOCAB / 128) {
            const unsigned sBnxt = sB0u + (unsigned)(((nc + 1) & 1) * 65536);
            const size_t nb = (size_t)(nc + 1) * 128;
#pragma unroll
            for (int i = 0; i < 16; i++) {
                int c   = i * 256 + tid;
                int row = c >> 5;
                int c16 = c & 31;
                cp16(sBnxt + swz(row, c16 * 16), g_B + (nb + row) * KDIM + c16 * 8);
            }
        }
        CP_COMMIT();

        const int n0 = nc * 128;
        // ---- init acc with -0.5*cnorm (folds distance into the GEMM) ----
        float acc[2][8][4];
#pragma unroll
        for (int nf = 0; nf < 8; nf++) {
            float2 cn = *(const float2*)&g_cnorm[n0 + colb + nf * 8];
            float ax = -0.5f * cn.x, ay = -0.5f * cn.y;
            acc[0][nf][0] = ax; acc[0][nf][1] = ay; acc[0][nf][2] = ax; acc[0][nf][3] = ay;
            acc[1][nf][0] = ax; acc[1][nf][1] = ay; acc[1][nf][2] = ax; acc[1][nf][3] = ay;
        }

        // ---- 16 k-steps over resident A and current B buffer ----
#pragma unroll
        for (int ks = 0; ks < 16; ks++) {
            unsigned a[2][4], b[8][2];
            const int kbyt = ks * 32 + (lane >> 4) * 16;
#pragma unroll
            for (int f = 0; f < 2; f++) {
                int row = wm + f * 16 + (lane & 15);
                ldsm4(a[f][0], a[f][1], a[f][2], a[f][3], sAu + swz(row, kbyt));
            }
#pragma unroll
            for (int j = 0; j < 4; j++) {
                int row = wn + j * 16 + (lane & 15);
                unsigned r0, r1, r2, r3;
                ldsm4(r0, r1, r2, r3, sBcur + swz(row, kbyt));
                b[2 * j][0] = r0; b[2 * j + 1][0] = r1;
                b[2 * j][1] = r2; b[2 * j + 1][1] = r3;
            }
#pragma unroll
            for (int f = 0; f < 2; f++)
#pragma unroll
                for (int n = 0; n < 8; n++)
                    mma16816(acc[f][n], a[f], b[n]);
        }

        // ---- top-3 update (maximize score) ----
#pragma unroll
        for (int nf = 0; nf < 8; nf++)
#pragma unroll
            for (int e = 0; e < 2; e++) {
                int code = n0 + colb + nf * 8 + e;
#pragma unroll
                for (int f = 0; f < 2; f++)
#pragma unroll
                    for (int half = 0; half < 2; half++) {
                        int slot = f * 2 + half;
                        float sc = acc[f][nf][half * 2 + e];
                        INS3(sc, code, slot);
                    }
            }

        CP_WAIT0();
        __syncthreads();
    }

    // ---- quad merge (lanes sharing the same rows) ----
#pragma unroll
    for (int s = 0; s < 4; s++) {
#pragma unroll
        for (int x = 1; x <= 2; x <<= 1) {
            float ov1 = __shfl_xor_sync(0xffffffffu, run_v1[s], x);
            int   oi1 = __shfl_xor_sync(0xffffffffu, run_i1[s], x);
            float ov2 = __shfl_xor_sync(0xffffffffu, run_v2[s], x);
            int   oi2 = __shfl_xor_sync(0xffffffffu, run_i2[s], x);
            float ov3 = __shfl_xor_sync(0xffffffffu, run_v3[s], x);
            int   oi3 = __shfl_xor_sync(0xffffffffu, run_i3[s], x);
            INS3(ov1, oi1, s);
            INS3(ov2, oi2, s);
            INS3(ov3, oi3, s);
        }
    }

    // ---- stash per-(row, warpN) top-3; cross-warpN merge to global top-4 ----
    float* s_mv = (float*)dsm;                 // 128*2*3 floats
    int*   s_mi = (int*)(dsm + 4096);          // 128*2*3 ints
    __syncthreads();                           // sA/sB no longer needed
    if ((lane & 3) == 0) {
#pragma unroll
        for (int s = 0; s < 4; s++) {
            int r = wm + (s >> 1) * 16 + (lane >> 2) + (s & 1) * 8;
            int w = warp & 1;
            int base = (r * 2 + w) * 3;
            s_mv[base + 0] = run_v1[s]; s_mi[base + 0] = run_i1[s];
            s_mv[base + 1] = run_v2[s]; s_mi[base + 1] = run_i2[s];
            s_mv[base + 2] = run_v3[s]; s_mi[base + 2] = run_i3[s];
        }
    }
    __syncthreads();
    if (tid < 128) {
        float bv[4] = {-3.4e38f, -3.4e38f, -3.4e38f, -3.4e38f};
        int   bi[4] = {0, 0, 0, 0};
#pragma unroll
        for (int w = 0; w < 2; w++)
#pragma unroll
            for (int r = 0; r < 3; r++) {
                float v = s_mv[(tid * 2 + w) * 3 + r];
                int   x = s_mi[(tid * 2 + w) * 3 + r];
                if (v > bv[0]) { bv[3]=bv[2]; bi[3]=bi[2]; bv[2]=bv[1]; bi[2]=bi[1];
                                 bv[1]=bv[0]; bi[1]=bi[0]; bv[0]=v; bi[0]=x; }
                else if (v > bv[1]) { bv[3]=bv[2]; bi[3]=bi[2]; bv[2]=bv[1]; bi[2]=bi[1];
                                      bv[1]=v; bi[1]=x; }
                else if (v > bv[2]) { bv[3]=bv[2]; bi[3]=bi[2]; bv[2]=v; bi[2]=x; }
                else if (v > bv[3]) { bv[3]=v; bi[3]=x; }
            }
        g_top4[m0 + tid] = make_int4(bi[0], bi[1], bi[2], bi[3]);
    }
}

// ---------------------------------------------------------------------------
// zero loss slot
// ---------------------------------------------------------------------------
__global__ void zero_loss_kernel(float* out, long long loss_off, long long osz) {
    if (loss_off >= 0 && loss_off < osz) out[loss_off] = 0.f;
}

// ---------------------------------------------------------------------------
// Epilogue: exact fp32 rescore of 4 candidates, winner gather + planar
// proposal + salience + vq_loss. One warp per token.
// ---------------------------------------------------------------------------
__global__ void epilogue_kernel(const float* __restrict__ gr,
                                const float* __restrict__ gi,
                                const float* __restrict__ cb,
                                const float* __restrict__ salw,
                                const float* __restrict__ salb,
                                float* __restrict__ out,
                                long long rbase, long long ibase,
                                long long sal_off, long long loss_off,
                                long long osz) {
    int token = (blockIdx.x * blockDim.x + threadIdx.x) >> 5;
    int lane  = threadIdx.x & 31;
    int wid   = threadIdx.x >> 5;
    __shared__ float lsum[8];

    float losspart = 0.f;
    if (token < NT) {
        int4 c4 = g_top4[token];
        int cand[4] = {c4.x, c4.y, c4.z, c4.w};
        // z as concatenated 256-vector in regs
        float zk[8];
#pragma unroll
        for (int w = 0; w < 8; w++) {
            int k = w * 32 + lane;
            zk[w] = (k < HALF) ? gr[(size_t)token * HALF + k]
                               : gi[(size_t)token * HALF + (k - HALF)];
        }
        float dot[4] = {0.f, 0.f, 0.f, 0.f};
#pragma unroll
        for (int j = 0; j < 4; j++) {
            const float* row = cb + (size_t)cand[j] * KDIM;
#pragma unroll
            for (int w = 0; w < 8; w++)
                dot[j] += zk[w] * row[w * 32 + lane];
        }
#pragma unroll
        for (int o = 16; o; o >>= 1) {
#pragma unroll
            for (int j = 0; j < 4; j++)
                dot[j] += __shfl_xor_sync(0xffffffffu, dot[j], o);
        }
        float dbest = 0.f; int ibest = -1;
#pragma unroll
        for (int j = 0; j < 4; j++) {
            float d = g_cnorm[cand[j]] - 2.0f * dot[j];
            if (ibest < 0 || d < dbest || (d == dbest && cand[j] < ibest)) {
                dbest = d; ibest = cand[j];
            }
        }
        const float* cw = cb + (size_t)ibest * KDIM;
        float salpart = 0.f;
#pragma unroll
        for (int w = 0; w < 4; w++) {
            int d = w * 32 + lane;
            float cr = cw[d];
            float ci = cw[HALF + d];
            float zr = zk[w];
            float zi = zk[w + 4];
            float vr = zr + (cr - zr);
            float vi = zi + (ci - zi);
            long long ro = rbase + (long long)token * HALF + d;
            if (ro < osz) out[ro] = vr;
            if (ibase >= 0) {
                long long io = ibase + (long long)token * HALF + d;
                if (io < osz) out[io] = vi;
            }
            float dr = cr - zr, di = ci - zi;
            losspart += dr * dr + di * di;
            salpart  += vr * salw[d] + vi * salw[HALF + d];
        }
#pragma unroll
        for (int o = 16; o; o >>= 1) {
            losspart += __shfl_xor_sync(0xffffffffu, losspart, o);
            salpart  += __shfl_xor_sync(0xffffffffu, salpart, o);
        }
        if (lane == 0 && sal_off + token < osz)
            out[sal_off + token] = salpart + salb[0];
    } else {
#pragma unroll
        for (int o = 16; o; o >>= 1)
            losspart += __shfl_xor_sync(0xffffffffu, losspart, o);
    }

    if (lane == 0) lsum[wid] = losspart;
    __syncthreads();
    if (threadIdx.x == 0 && loss_off < osz) {
        float s = 0.f;
#pragma unroll
        for (int i = 0; i < 8; i++) s += lsum[i];
        atomicAdd(out + loss_off, s * (1.25f / (float)(NT * KDIM)));
    }
}

// ---------------------------------------------------------------------------
extern "C" void kernel_launch(void* const* d_in, const int* in_sizes, int n_in,
                              void* d_out, int out_size) {
    // Signature-order binding (validated R10): gw_real, gw_imag, codebook, sal_w, sal_b
    const float* gw_real  = 0;
    const float* gw_imag  = 0;
    const float* codebook = 0;
    const float* sal_w    = 0;
    const float* sal_b    = 0;
    for (int i = 0; i < n_in; i++) {
        int s = in_sizes[i];
        const float* p = (const float*)d_in[i];
        if (s == NT * HALF) { if (!gw_real) gw_real = p; else gw_imag = p; }
        else if (s == VOCAB * KDIM) codebook = p;
        else if (s == KDIM)         sal_w = p;
        else if (s == 1)            sal_b = p;
    }
    float* out = (float*)d_out;
    long long osz = (long long)out_size;

    // Planar output layout (validated R10)
    long long rbase = 0, ibase, sal_off, loss_off;
    const long long PLANE = (long long)NT * HALF;
    if (osz >= 2 * PLANE) { ibase = PLANE; sal_off = 2 * PLANE; loss_off = 2 * PLANE + NT; }
    else                  { ibase = -1;    sal_off = PLANE;     loss_off = PLANE + NT; }

    convertA_kernel<<<(NT * 64) / 256, 256>>>(gw_real, gw_imag);
    convertB_kernel<<<(VOCAB * 128) / 256, 256>>>(codebook);
    cnorm_kernel<<<VOCAB / 8, 256>>>(codebook);

    cudaFuncSetAttribute(coarse_kernel,
                         cudaFuncAttributeMaxDynamicSharedMemorySize, 196608);
    coarse_kernel<<<NT / 128, 256, 196608>>>();

    zero_loss_kernel<<<1, 1>>>(out, loss_off, osz);
    epilogue_kernel<<<NT / 8, 256>>>(gw_real, gw_imag, codebook,
                                     sal_w, sal_b, out,
                                     rbase, ibase, sal_off, loss_off, osz);
}

// round 17
// speedup vs baseline: 7.5053x; 1.6488x over previous
#include <cuda_runtime.h>
#include <cuda_bf16.h>

// Problem constants
#define NT    32768      // B*S tokens
#define KDIM  256        // 2*DIM
#define HALF  128        // DIM
#define VOCAB 8192
#define KB    512        // bytes per smem row (256 bf16)

#define IDXMASK 0x1FFF           // 13 bits: VOCAB indices 0..8191
#define VALMASK 0xFFFFE000u

// Scratch (no cudaMalloc allowed)
__device__ float g_cnorm[VOCAB];
__device__ int4  g_top4[NT];                         // top-4 coarse candidates
__device__ __nv_bfloat16 g_A[(size_t)NT * KDIM];     // 16.8 MB
__device__ __nv_bfloat16 g_B[(size_t)VOCAB * KDIM];  // 4.2 MB

// ---------------------------------------------------------------------------
// smem swizzle for 512B rows: XOR col bits[6:4] with row bits[2:0]
// ---------------------------------------------------------------------------
__device__ __forceinline__ unsigned swz(int row, int colByte) {
    return (unsigned)(row * KB + (colByte ^ ((row & 7) << 4)));
}

__device__ __forceinline__ void ldsm4(unsigned& r0, unsigned& r1,
                                      unsigned& r2, unsigned& r3, unsigned addr) {
    asm volatile("ldmatrix.sync.aligned.m8n8.x4.shared.b16 {%0,%1,%2,%3}, [%4];"
                 : "=r"(r0), "=r"(r1), "=r"(r2), "=r"(r3) : "r"(addr));
}
__device__ __forceinline__ void mma16816(float* c, const unsigned* a, const unsigned* b) {
    asm volatile("mma.sync.aligned.m16n8k16.row.col.f32.bf16.bf16.f32 "
                 "{%0,%1,%2,%3}, {%4,%5,%6,%7}, {%8,%9}, {%0,%1,%2,%3};"
                 : "+f"(c[0]), "+f"(c[1]), "+f"(c[2]), "+f"(c[3])
                 : "r"(a[0]), "r"(a[1]), "r"(a[2]), "r"(a[3]), "r"(b[0]), "r"(b[1]));
}
__device__ __forceinline__ void cp16(unsigned saddr, const void* gaddr) {
    asm volatile("cp.async.cg.shared.global [%0], [%1], 16;" :: "r"(saddr), "l"(gaddr));
}
#define CP_COMMIT() asm volatile("cp.async.commit_group;")
#define CP_WAIT0()  asm volatile("cp.async.wait_group 0;")

// Branchless top-3 insert (values carry packed indices in low mantissa bits)
#define NET3(s, v) do {                                   \
    float _n1 = fmaxf(run1[s], (v));                      \
    float _t  = fminf(run1[s], (v));                      \
    float _n2 = fmaxf(run2[s], _t);                       \
    float _t2 = fminf(run2[s], _t);                       \
    float _n3 = fmaxf(run3[s], _t2);                      \
    run1[s] = _n1; run2[s] = _n2; run3[s] = _n3; } while (0)

// ---------------------------------------------------------------------------
// Convert kernels: fp32 -> bf16 (pure, no split)
// ---------------------------------------------------------------------------
__global__ void convertA_kernel(const float* __restrict__ gr,
                                const float* __restrict__ gi) {
    int id = blockIdx.x * blockDim.x + threadIdx.x;   // NT*64
    int t  = id >> 6;
    int d2 = (id & 63) * 2;
    float2 r  = *(const float2*)(gr + (size_t)t * HALF + d2);
    float2 im = *(const float2*)(gi + (size_t)t * HALF + d2);
    __nv_bfloat162 rh, ih;
    rh.x = __float2bfloat16(r.x);  rh.y = __float2bfloat16(r.y);
    ih.x = __float2bfloat16(im.x); ih.y = __float2bfloat16(im.y);
    __nv_bfloat16* A = g_A + (size_t)t * KDIM;
    *(__nv_bfloat162*)(A + d2)        = rh;
    *(__nv_bfloat162*)(A + HALF + d2) = ih;
}

__global__ void convertB_kernel(const float* __restrict__ cb) {
    int id = blockIdx.x * blockDim.x + threadIdx.x;   // VOCAB*128
    int v  = id >> 7;
    int k2 = (id & 127) * 2;
    float2 c = *(const float2*)(cb + (size_t)v * KDIM + k2);
    __nv_bfloat162 ch;
    ch.x = __float2bfloat16(c.x); ch.y = __float2bfloat16(c.y);
    *(__nv_bfloat162*)(g_B + (size_t)v * KDIM + k2) = ch;
}

// ---------------------------------------------------------------------------
// cnorm: exact fp32 codebook row norms
// ---------------------------------------------------------------------------
__global__ void cnorm_kernel(const float* __restrict__ cb) {
    int row  = (blockIdx.x * blockDim.x + threadIdx.x) >> 5;
    int lane = threadIdx.x & 31;
    if (row >= VOCAB) return;
    const float* r = cb + (size_t)row * KDIM;
    float s = 0.f;
#pragma unroll
    for (int j = 0; j < 8; j++) { float v = r[j * 32 + lane]; s += v * v; }
#pragma unroll
    for (int o = 16; o; o >>= 1) s += __shfl_xor_sync(0xffffffffu, s, o);
    if (lane == 0) g_cnorm[row] = s;
}

// ---------------------------------------------------------------------------
// Coarse GEMM + branchless top-3 argmin. Pure bf16, K=256.
// CTA: 128 tokens, A resident in smem; vocab streamed 128 codes/chunk with
// cp.async double buffering. 8 warps = 4(M) x 2(N), warp tile 32x64.
// Score = -0.5*||c||^2 + z.c  (maximize); index packed into mantissa lsbs.
// ---------------------------------------------------------------------------
__global__ __launch_bounds__(256, 1)
void coarse_kernel() {
    extern __shared__ char dsm[];
    // [0,64K): sA   [64K,128K): sB0   [128K,192K): sB1
    const unsigned sAu  = (unsigned)__cvta_generic_to_shared(dsm);
    const unsigned sB0u = sAu + 65536;

    const int tid  = threadIdx.x;
    const int lane = tid & 31;
    const int warp = tid >> 5;
    const int wm   = (warp >> 1) * 32;
    const int wn   = (warp & 1) * 64;
    const size_t m0 = (size_t)blockIdx.x * 128;

    // ---- prologue: A tile (whole K) + first B tile via cp.async ----
#pragma unroll
    for (int i = 0; i < 16; i++) {
        int c   = i * 256 + tid;      // 0..4095 16B chunks
        int row = c >> 5;
        int c16 = c & 31;
        cp16(sAu + swz(row, c16 * 16),  g_A + (m0 + row) * KDIM + c16 * 8);
        cp16(sB0u + swz(row, c16 * 16), g_B + (size_t)row * KDIM + c16 * 8);
    }
    CP_COMMIT();
    CP_WAIT0();
    __syncthreads();

    float run1[4], run2[4], run3[4];    // packed (value|index), descending
#pragma unroll
    for (int s = 0; s < 4; s++) { run1[s] = -3.4e38f; run2[s] = -3.4e38f; run3[s] = -3.4e38f; }

    const int colb = wn + (lane & 3) * 2;   // thread's even col base within tile

    for (int nc = 0; nc < VOCAB / 128; nc++) {
        const unsigned sBcur = sB0u + (unsigned)((nc & 1) * 65536);
        // prefetch next B tile into the other buffer
        if (nc + 1 < VOCAB / 128) {
            const unsigned sBnxt = sB0u + (unsigned)(((nc + 1) & 1) * 65536);
            const size_t nb = (size_t)(nc + 1) * 128;
#pragma unroll
            for (int i = 0; i < 16; i++) {
                int c   = i * 256 + tid;
                int row = c >> 5;
                int c16 = c & 31;
                cp16(sBnxt + swz(row, c16 * 16), g_B + (nb + row) * KDIM + c16 * 8);
            }
        }
        CP_COMMIT();

        const int n0 = nc * 128;
        // ---- init acc with -0.5*cnorm (folds distance into the GEMM) ----
        float acc[2][8][4];
#pragma unroll
        for (int nf = 0; nf < 8; nf++) {
            float2 cn = *(const float2*)&g_cnorm[n0 + colb + nf * 8];
            float ax = -0.5f * cn.x, ay = -0.5f * cn.y;
            acc[0][nf][0] = ax; acc[0][nf][1] = ay; acc[0][nf][2] = ax; acc[0][nf][3] = ay;
            acc[1][nf][0] = ax; acc[1][nf][1] = ay; acc[1][nf][2] = ax; acc[1][nf][3] = ay;
        }

        // ---- 16 k-steps over resident A and current B buffer ----
#pragma unroll
        for (int ks = 0; ks < 16; ks++) {
            unsigned a[2][4], b[8][2];
            const int kbyt = ks * 32 + (lane >> 4) * 16;
#pragma unroll
            for (int f = 0; f < 2; f++) {
                int row = wm + f * 16 + (lane & 15);
                ldsm4(a[f][0], a[f][1], a[f][2], a[f][3], sAu + swz(row, kbyt));
            }
#pragma unroll
            for (int j = 0; j < 4; j++) {
                int row = wn + j * 16 + (lane & 15);
                unsigned r0, r1, r2, r3;
                ldsm4(r0, r1, r2, r3, sBcur + swz(row, kbyt));
                b[2 * j][0] = r0; b[2 * j + 1][0] = r1;
                b[2 * j][1] = r2; b[2 * j + 1][1] = r3;
            }
#pragma unroll
            for (int f = 0; f < 2; f++)
#pragma unroll
                for (int n = 0; n < 8; n++)
                    mma16816(acc[f][n], a[f], b[n]);
        }

        // ---- branchless top-3 update with packed index ----
        const int cb0 = n0 + colb;   // invariant base this chunk
#pragma unroll
        for (int nf = 0; nf < 8; nf++)
#pragma unroll
            for (int e = 0; e < 2; e++) {
                const int code = cb0 + nf * 8 + e;   // IADD3 (imm offset)
#pragma unroll
                for (int f = 0; f < 2; f++)
#pragma unroll
                    for (int half = 0; half < 2; half++) {
                        const int slot = f * 2 + half;
                        float sc = acc[f][nf][half * 2 + e];
                        float sp = __int_as_float((__float_as_int(sc) & VALMASK) | code);
                        NET3(slot, sp);
                    }
            }

        CP_WAIT0();
        __syncthreads();
    }

    // ---- quad merge (lanes sharing the same token rows) ----
#pragma unroll
    for (int s = 0; s < 4; s++) {
#pragma unroll
        for (int x = 1; x <= 2; x <<= 1) {
            float o1 = __shfl_xor_sync(0xffffffffu, run1[s], x);
            float o2 = __shfl_xor_sync(0xffffffffu, run2[s], x);
            float o3 = __shfl_xor_sync(0xffffffffu, run3[s], x);
            NET3(s, o1);
            NET3(s, o2);
            NET3(s, o3);
        }
    }

    // ---- stash per-(row, warpN) top-3; cross-warpN merge to global top-4 ----
    float* s_mv = (float*)dsm;                 // 128*2*3 packed floats
    __syncthreads();                           // sA/sB no longer needed
    if ((lane & 3) == 0) {
#pragma unroll
        for (int s = 0; s < 4; s++) {
            int r = wm + (s >> 1) * 16 + (lane >> 2) + (s & 1) * 8;
            int w = warp & 1;
            int base = (r * 2 + w) * 3;
            s_mv[base + 0] = run1[s];
            s_mv[base + 1] = run2[s];
            s_mv[base + 2] = run3[s];
        }
    }
    __syncthreads();
    if (tid < 128) {
        float b1 = -3.4e38f, b2 = -3.4e38f, b3 = -3.4e38f, b4 = -3.4e38f;
#pragma unroll
        for (int w = 0; w < 2; w++)
#pragma unroll
            for (int r = 0; r < 3; r++) {
                float v = s_mv[(tid * 2 + w) * 3 + r];
                float n1 = fmaxf(b1, v);  float t  = fminf(b1, v);
                float n2 = fmaxf(b2, t);  float t2 = fminf(b2, t);
                float n3 = fmaxf(b3, t2); float t3 = fminf(b3, t2);
                float n4 = fmaxf(b4, t3);
                b1 = n1; b2 = n2; b3 = n3; b4 = n4;
            }
        g_top4[m0 + tid] = make_int4(__float_as_int(b1) & IDXMASK,
                                     __float_as_int(b2) & IDXMASK,
                                     __float_as_int(b3) & IDXMASK,
                                     __float_as_int(b4) & IDXMASK);
    }
}

// ---------------------------------------------------------------------------
// zero loss slot
// ---------------------------------------------------------------------------
__global__ void zero_loss_kernel(float* out, long long loss_off, long long osz) {
    if (loss_off >= 0 && loss_off < osz) out[loss_off] = 0.f;
}

// ---------------------------------------------------------------------------
// Epilogue: exact fp32 rescore of 4 candidates, winner gather + planar
// proposal + salience + vq_loss. One warp per token.
// ---------------------------------------------------------------------------
__global__ void epilogue_kernel(const float* __restrict__ gr,
                                const float* __restrict__ gi,
                                const float* __restrict__ cb,
                                const float* __restrict__ salw,
                                const float* __restrict__ salb,
                                float* __restrict__ out,
                                long long rbase, long long ibase,
                                long long sal_off, long long loss_off,
                                long long osz) {
    int token = (blockIdx.x * blockDim.x + threadIdx.x) >> 5;
    int lane  = threadIdx.x & 31;
    int wid   = threadIdx.x >> 5;
    __shared__ float lsum[8];

    float losspart = 0.f;
    if (token < NT) {
        int4 c4 = g_top4[token];
        int cand[4] = {c4.x, c4.y, c4.z, c4.w};
        float zk[8];
#pragma unroll
        for (int w = 0; w < 8; w++) {
            int k = w * 32 + lane;
            zk[w] = (k < HALF) ? gr[(size_t)token * HALF + k]
                               : gi[(size_t)token * HALF + (k - HALF)];
        }
        float dot[4] = {0.f, 0.f, 0.f, 0.f};
#pragma unroll
        for (int j = 0; j < 4; j++) {
            const float* row = cb + (size_t)cand[j] * KDIM;
#pragma unroll
            for (int w = 0; w < 8; w++)
                dot[j] += zk[w] * row[w * 32 + lane];
        }
#pragma unroll
        for (int o = 16; o; o >>= 1) {
#pragma unroll
            for (int j = 0; j < 4; j++)
                dot[j] += __shfl_xor_sync(0xffffffffu, dot[j], o);
        }
        float dbest = 0.f; int ibest = -1;
#pragma unroll
        for (int j = 0; j < 4; j++) {
            float d = g_cnorm[cand[j]] - 2.0f * dot[j];
            if (ibest < 0 || d < dbest || (d == dbest && cand[j] < ibest)) {
                dbest = d; ibest = cand[j];
            }
        }
        const float* cw = cb + (size_t)ibest * KDIM;
        float salpart = 0.f;
#pragma unroll
        for (int w = 0; w < 4; w++) {
            int d = w * 32 + lane;
            float cr = cw[d];
            float ci = cw[HALF + d];
            float zr = zk[w];
            float zi = zk[w + 4];
            float vr = zr + (cr - zr);
            float vi = zi + (ci - zi);
            long long ro = rbase + (long long)token * HALF + d;
            if (ro < osz) out[ro] = vr;
            if (ibase >= 0) {
                long long io = ibase + (long long)token * HALF + d;
                if (io < osz) out[io] = vi;
            }
            float dr = cr - zr, di = ci - zi;
            losspart += dr * dr + di * di;
            salpart  += vr * salw[d] + vi * salw[HALF + d];
        }
#pragma unroll
        for (int o = 16; o; o >>= 1) {
            losspart += __shfl_xor_sync(0xffffffffu, losspart, o);
            salpart  += __shfl_xor_sync(0xffffffffu, salpart, o);
        }
        if (lane == 0 && sal_off + token < osz)
            out[sal_off + token] = salpart + salb[0];
    } else {
#pragma unroll
        for (int o = 16; o; o >>= 1)
            losspart += __shfl_xor_sync(0xffffffffu, losspart, o);
    }

    if (lane == 0) lsum[wid] = losspart;
    __syncthreads();
    if (threadIdx.x == 0 && loss_off < osz) {
        float s = 0.f;
#pragma unroll
        for (int i = 0; i < 8; i++) s += lsum[i];
        atomicAdd(out + loss_off, s * (1.25f / (float)(NT * KDIM)));
    }
}

// ---------------------------------------------------------------------------
extern "C" void kernel_launch(void* const* d_in, const int* in_sizes, int n_in,
                              void* d_out, int out_size) {
    // Signature-order binding (validated R10): gw_real, gw_imag, codebook, sal_w, sal_b
    const float* gw_real  = 0;
    const float* gw_imag  = 0;
    const float* codebook = 0;
    const float* sal_w    = 0;
    const float* sal_b    = 0;
    for (int i = 0; i < n_in; i++) {
        int s = in_sizes[i];
        const float* p = (const float*)d_in[i];
        if (s == NT * HALF) { if (!gw_real) gw_real = p; else gw_imag = p; }
        else if (s == VOCAB * KDIM) codebook = p;
        else if (s == KDIM)         sal_w = p;
        else if (s == 1)            sal_b = p;
    }
    float* out = (float*)d_out;
    long long osz = (long long)out_size;

    // Planar output layout (validated R10)
    long long rbase = 0, ibase, sal_off, loss_off;
    const long long PLANE = (long long)NT * HALF;
    if (osz >= 2 * PLANE) { ibase = PLANE; sal_off = 2 * PLANE; loss_off = 2 * PLANE + NT; }
    else                  { ibase = -1;    sal_off = PLANE;     loss_off = PLANE + NT; }

    convertA_kernel<<<(NT * 64) / 256, 256>>>(gw_real, gw_imag);
    convertB_kernel<<<(VOCAB * 128) / 256, 256>>>(codebook);
    cnorm_kernel<<<VOCAB / 8, 256>>>(codebook);

    cudaFuncSetAttribute(coarse_kernel,
                         cudaFuncAttributeMaxDynamicSharedMemorySize, 196608);
    coarse_kernel<<<NT / 128, 256, 196608>>>();

    zero_loss_kernel<<<1, 1>>>(out, loss_off, osz);
    epilogue_kernel<<<NT / 8, 256>>>(gw_real, gw_imag, codebook,
                                     sal_w, sal_b, out,
                                     rbase, ibase, sal_off, loss_off, osz);
}